// round 13
// baseline (speedup 1.0000x reference)
#include <cuda_runtime.h>
#include <cstdint>
#include <math.h>

// QKV attention, full fp16 mma.sync m16n8k16 (fp32 accum), chunk-interleaved:
// per 16-key chunk do GEMM1 -> ex2 softmax -> pack -> GEMM2, so S-fragments
// are transient (16 regs). 4 warps, warp tile 32x64, 3 CTAs/SM target.
// qkv (4, 3*1024, 1024) fp32, 16 heads, d=64. CTA = 128 queries x full seq.

#define NSEQ 1024
#define TQ   128
#define TK   64
#define NTHREADS 128

// smem (uint32 units): Ks16[64][32] @0 (8KB) | Vs16[64][32] @2048 (8KB) |
// mask @4096. Qs16[128][32] staging (16KB) and Os fp32 [64][128] (32KB,
// epilogue) alias from 0. Total 32KB.
#define OU_K 0
#define OU_V 2048
#define OU_M 4096
#define SMEM_BYTES 32768

// Q scale: 1/sqrt(64) * log2(e) folded in -> softmax is bare ex2
#define QSCALE 0.18033688011112042f

__device__ __forceinline__ uint32_t pack_h2(float lo, float hi) {
    uint32_t r; asm("cvt.rn.f16x2.f32 %0, %1, %2;" : "=r"(r) : "f"(hi), "f"(lo));
    return r;
}
__device__ __forceinline__ float ex2f(float x) {
    float r; asm("ex2.approx.f32 %0, %1;" : "=f"(r) : "f"(x)); return r;
}

#define MMA_F16(c, a, b0, b1) \
    asm volatile("mma.sync.aligned.m16n8k16.row.col.f32.f16.f16.f32 " \
        "{%0,%1,%2,%3}, {%4,%5,%6,%7}, {%8,%9}, {%0,%1,%2,%3};" \
        : "+f"((c)[0]), "+f"((c)[1]), "+f"((c)[2]), "+f"((c)[3]) \
        : "r"((a)[0]), "r"((a)[1]), "r"((a)[2]), "r"((a)[3]), "r"(b0), "r"(b1))

extern __shared__ float smem[];

__global__ void __launch_bounds__(NTHREADS, 3)
attn_mma_kernel(const float* __restrict__ qkv,
                const unsigned int* __restrict__ mask,
                float* __restrict__ out)
{
    uint32_t* Ksu = (uint32_t*)smem + OU_K;
    uint32_t* Vsu = (uint32_t*)smem + OU_V;
    unsigned int* mS = (unsigned int*)smem + OU_M;

    const int tid  = threadIdx.x;
    const int lane = tid & 31;
    const int warp = tid >> 5;              // 0..3, rows 32*warp..+31
    const int grp  = lane >> 2;
    const int tg   = lane & 3;
    const int r0   = 32 * warp;

    const int bh = blockIdx.y, b = bh >> 4, h = bh & 15;
    const int i0 = blockIdx.x * TQ;

    const float* qb = qkv + ((size_t)b * 3072 + h * 64) * NSEQ;
    const float* kb = qb + (size_t)1024 * NSEQ;
    const float* vb = qb + (size_t)2048 * NSEQ;

    // ---- stage Q: rows=i (128), 32 d-pair cols, swizzle col ^ 4*(i&7) ----
    uint32_t* Qsu = (uint32_t*)smem;
    #pragma unroll
    for (int it = 0; it < 8; it++) {
        const int idx = it * NTHREADS + tid;   // 0..1023
        const int i   = idx & 127;
        const int g   = idx >> 7;              // d-octet
        const float* gp = qb + (size_t)(8 * g) * NSEQ + i0 + i;
        float v[8];
        #pragma unroll
        for (int s = 0; s < 8; s++) v[s] = gp[(size_t)s * NSEQ] * QSCALE;
        uint4 w;
        w.x = pack_h2(v[0], v[1]); w.y = pack_h2(v[2], v[3]);
        w.z = pack_h2(v[4], v[5]); w.w = pack_h2(v[6], v[7]);
        *(uint4*)(Qsu + i * 32 + ((4 * g) ^ (4 * (i & 7)))) = w;
    }
    __syncthreads();

    // ---- Q fragments -> registers (32 regs: fp16x2 pairs along d) ----
    uint32_t qf[2][4][4];
    {
        const int sw = 4 * grp;
        #pragma unroll
        for (int mt = 0; mt < 2; mt++) {
            const int row = r0 + 16 * mt + grp;
            const uint32_t* q0 = Qsu + row * 32;
            const uint32_t* q1 = q0 + 8 * 32;
            #pragma unroll
            for (int ks = 0; ks < 4; ks++) {
                qf[mt][ks][0] = q0[(8 * ks + tg) ^ sw];
                qf[mt][ks][1] = q1[(8 * ks + tg) ^ sw];
                qf[mt][ks][2] = q0[(8 * ks + 4 + tg) ^ sw];
                qf[mt][ks][3] = q1[(8 * ks + 4 + tg) ^ sw];
            }
        }
    }
    __syncthreads();   // Qs dead; Ks/Vs region usable

    float so[2][8][4];
    #pragma unroll
    for (int mt = 0; mt < 2; mt++)
        #pragma unroll
        for (int f = 0; f < 8; f++)
            #pragma unroll
            for (int r = 0; r < 4; r++) so[mt][f][r] = 0.f;
    float lr[2][2] = {{0.f, 0.f}, {0.f, 0.f}};

    for (int t = 0; t < 16; t++) {
        const int j0 = t * TK;
        __syncthreads();   // prev tile's GEMMs done reading Ks/Vs

        // ---- K fill: rows=j, cols=d-pairs, swizzle col ^ 4*(j&7) ----
        #pragma unroll
        for (int it = 0; it < 4; it++) {
            const int idx = it * NTHREADS + tid;   // 0..511
            const int j   = idx & 63;
            const int g   = idx >> 6;              // d-octet
            const float* gp = kb + (size_t)(8 * g) * NSEQ + j0 + j;
            float v[8];
            #pragma unroll
            for (int s = 0; s < 8; s++) v[s] = gp[(size_t)s * NSEQ];
            uint4 w;
            w.x = pack_h2(v[0], v[1]); w.y = pack_h2(v[2], v[3]);
            w.z = pack_h2(v[4], v[5]); w.w = pack_h2(v[6], v[7]);
            *(uint4*)(Ksu + j * 32 + ((4 * g) ^ (4 * (j & 7)))) = w;
        }
        // ---- V fill: rows=dd, cols=j-pairs, swizzle col ^ 4*(dd&7) ----
        #pragma unroll
        for (int it = 0; it < 4; it++) {
            const int idx = it * NTHREADS + tid;   // 0..511
            const int dd  = idx >> 3;
            const int g   = idx & 7;               // j-octet
            const float* vp = vb + (size_t)dd * NSEQ + j0 + 8 * g;
            const float4 v0 = *(const float4*)(vp);
            const float4 v1 = *(const float4*)(vp + 4);
            uint4 w;
            w.x = pack_h2(v0.x, v0.y); w.y = pack_h2(v0.z, v0.w);
            w.z = pack_h2(v1.x, v1.y); w.w = pack_h2(v1.z, v1.w);
            *(uint4*)(Vsu + dd * 32 + ((4 * g) ^ (4 * (dd & 7)))) = w;
        }
        if (tid < TK) mS[tid] = mask[b * NSEQ + j0 + tid];
        __syncthreads();

        const int swb = 4 * grp;

        // ---- per 16-key chunk: GEMM1 -> softmax -> pack -> GEMM2 ----
        #pragma unroll
        for (int kp = 0; kp < 4; kp++) {
            // GEMM1 chunk: S[:, 16kp..16kp+16), 16 MMAs
            float sc[2][2][4];
            #pragma unroll
            for (int mt = 0; mt < 2; mt++)
                #pragma unroll
                for (int f2 = 0; f2 < 2; f2++)
                    #pragma unroll
                    for (int r = 0; r < 4; r++) sc[mt][f2][r] = 0.f;

            #pragma unroll
            for (int ks = 0; ks < 4; ks++) {
                #pragma unroll
                for (int f2 = 0; f2 < 2; f2++) {
                    const uint32_t* krow = Ksu + (16 * kp + 8 * f2 + grp) * 32;
                    const uint32_t b0 = krow[(8 * ks + tg) ^ swb];
                    const uint32_t b1 = krow[(8 * ks + 4 + tg) ^ swb];
                    MMA_F16(sc[0][f2], qf[0][ks], b0, b1);
                    MMA_F16(sc[1][f2], qf[1][ks], b0, b1);
                }
            }

            // softmax chunk (bare ex2; log2e pre-folded into Q)
            #pragma unroll
            for (int f2 = 0; f2 < 2; f2++) {
                const int c0 = 16 * kp + 8 * f2 + 2 * tg;
                const bool m0 = (mS[c0] != 0u), m1 = (mS[c0 + 1] != 0u);
                #pragma unroll
                for (int mt = 0; mt < 2; mt++) {
                    const float p0 = m0 ? ex2f(sc[mt][f2][0]) : 0.f;
                    const float p1 = m1 ? ex2f(sc[mt][f2][1]) : 0.f;
                    const float p2 = m0 ? ex2f(sc[mt][f2][2]) : 0.f;
                    const float p3 = m1 ? ex2f(sc[mt][f2][3]) : 0.f;
                    lr[mt][0] += p0 + p1;
                    lr[mt][1] += p2 + p3;
                    sc[mt][f2][0] = p0; sc[mt][f2][1] = p1;
                    sc[mt][f2][2] = p2; sc[mt][f2][3] = p3;
                }
            }

            // pack chunk A-frags (C-frag layout == A-frag layout)
            uint32_t a[2][4];
            #pragma unroll
            for (int mt = 0; mt < 2; mt++) {
                a[mt][0] = pack_h2(sc[mt][0][0], sc[mt][0][1]);
                a[mt][1] = pack_h2(sc[mt][0][2], sc[mt][0][3]);
                a[mt][2] = pack_h2(sc[mt][1][0], sc[mt][1][1]);
                a[mt][3] = pack_h2(sc[mt][1][2], sc[mt][1][3]);
            }

            // GEMM2 chunk: O += P[:, chunk] V^T[chunk, :], 16 MMAs
            #pragma unroll
            for (int f = 0; f < 8; f++) {
                const uint32_t* vrow = Vsu + (8 * f + grp) * 32;
                const uint32_t b0 = vrow[(8 * kp + tg)     ^ swb];
                const uint32_t b1 = vrow[(8 * kp + 4 + tg) ^ swb];
                MMA_F16(so[0][f], a[0], b0, b1);
                MMA_F16(so[1][f], a[1], b0, b1);
            }
        }
    }

    // ---- epilogue: l reduce, normalize, transpose via smem, coalesced store ----
    #pragma unroll
    for (int mt = 0; mt < 2; mt++)
        #pragma unroll
        for (int hh = 0; hh < 2; hh++) {
            lr[mt][hh] += __shfl_xor_sync(0xffffffffu, lr[mt][hh], 1);
            lr[mt][hh] += __shfl_xor_sync(0xffffffffu, lr[mt][hh], 2);
        }
    float inv[2][2];
    #pragma unroll
    for (int mt = 0; mt < 2; mt++) {
        inv[mt][0] = 1.0f / lr[mt][0];
        inv[mt][1] = 1.0f / lr[mt][1];
    }

    __syncthreads();   // all GEMM2 done; smem reusable
    float* Os = smem;  // [dd][i] 64x128 fp32, swizzle i' = i ^ ((dd&6)<<2)
    #pragma unroll
    for (int f = 0; f < 8; f++) {
        const int dd = 8 * f + 2 * tg;
        const int sw = (dd & 6) << 2;
        #pragma unroll
        for (int mt = 0; mt < 2; mt++) {
            const int row = (r0 + 16 * mt + grp) ^ sw;
            Os[dd * 128 + row]             = so[mt][f][0] * inv[mt][0];
            Os[(dd + 1) * 128 + row]       = so[mt][f][1] * inv[mt][0];
            Os[dd * 128 + (row ^ 8)]       = so[mt][f][2] * inv[mt][1];
            Os[(dd + 1) * 128 + (row ^ 8)] = so[mt][f][3] * inv[mt][1];
        }
    }
    __syncthreads();

    float* ob = out + ((size_t)b * 1024 + h * 64) * NSEQ + i0;
    #pragma unroll
    for (int it = 0; it < 16; it++) {
        const int lin = it * 512 + tid * 4;
        const int dd  = lin >> 7;
        const int c   = lin & 127;
        const float4 v = *(const float4*)(Os + dd * 128 + c);
        *(float4*)(ob + (size_t)dd * NSEQ + (c ^ ((dd & 6) << 2))) = v;
    }
}

extern "C" void kernel_launch(void* const* d_in, const int* in_sizes, int n_in,
                              void* d_out, int out_size)
{
    const float* qkv = (const float*)d_in[0];
    const unsigned int* mask = (const unsigned int*)d_in[1];
    float* out = (float*)d_out;

    cudaFuncSetAttribute(attn_mma_kernel,
                         cudaFuncAttributeMaxDynamicSharedMemorySize, SMEM_BYTES);

    dim3 grid(NSEQ / TQ, 64);
    attn_mma_kernel<<<grid, NTHREADS, SMEM_BYTES>>>(qkv, mask, out);
}

// round 14
// speedup vs baseline: 1.1896x; 1.1896x over previous
#include <cuda_runtime.h>
#include <cstdint>
#include <math.h>

// QKV attention, full fp16 mma.sync m16n8k16 (fp32 accum). R12 structure
// (4 warps, 32x64 warp tile, 16 independent GEMM1 chains) + double-buffered
// K/V with fill(t+1) issued AFTER P is packed (sc dead -> fits 255 regs),
// + ex2 softmax (log2e folded into Q scale). 1 sync/tile.
// qkv (4, 3*1024, 1024) fp32, 16 heads, d=64. CTA = 128 queries x full seq.

#define NSEQ 1024
#define TQ   128
#define TK   64
#define NTHREADS 128

// smem (uint32 units): buffer[2] of (Ks16[64][32] | Vs16[64][32]) = 8192 |
// mask[2][64] @8192. Qs16[128][32] staging (16KB) and Os fp32 [64][128]
// (32KB epilogue) alias the buffer region.
#define BUFU  4096            // uint32 per buffer (Ks 2048 + Vs 2048)
#define OU_M  8192
#define SMEM_BYTES ((8192 + 128) * 4)

// 1/sqrt(64) * log2(e): softmax is bare ex2
#define QSCALE 0.18033688011112042f

__device__ __forceinline__ uint32_t pack_h2(float lo, float hi) {
    uint32_t r; asm("cvt.rn.f16x2.f32 %0, %1, %2;" : "=r"(r) : "f"(hi), "f"(lo));
    return r;
}
__device__ __forceinline__ float ex2f(float x) {
    float r; asm("ex2.approx.f32 %0, %1;" : "=f"(r) : "f"(x)); return r;
}

#define MMA_F16(c, a, b0, b1) \
    asm volatile("mma.sync.aligned.m16n8k16.row.col.f32.f16.f16.f32 " \
        "{%0,%1,%2,%3}, {%4,%5,%6,%7}, {%8,%9}, {%0,%1,%2,%3};" \
        : "+f"((c)[0]), "+f"((c)[1]), "+f"((c)[2]), "+f"((c)[3]) \
        : "r"((a)[0]), "r"((a)[1]), "r"((a)[2]), "r"((a)[3]), "r"(b0), "r"(b1))

extern __shared__ float smem[];

__global__ void __launch_bounds__(NTHREADS, 2)
attn_mma_kernel(const float* __restrict__ qkv,
                const unsigned int* __restrict__ mask,
                float* __restrict__ out)
{
    uint32_t* Su = (uint32_t*)smem;
    unsigned int* mS = Su + OU_M;

    const int tid  = threadIdx.x;
    const int lane = tid & 31;
    const int warp = tid >> 5;              // 0..3, rows 32*warp..+31
    const int grp  = lane >> 2;
    const int tg   = lane & 3;
    const int r0   = 32 * warp;

    const int bh = blockIdx.y, b = bh >> 4, h = bh & 15;
    const int i0 = blockIdx.x * TQ;

    const float* qb = qkv + ((size_t)b * 3072 + h * 64) * NSEQ;
    const float* kb = qb + (size_t)1024 * NSEQ;
    const float* vb = qb + (size_t)2048 * NSEQ;

    // ---- stage Q: rows=i (128), 32 d-pair cols, swizzle col ^ 4*(i&7) ----
    #pragma unroll
    for (int it = 0; it < 8; it++) {
        const int idx = it * NTHREADS + tid;   // 0..1023
        const int i   = idx & 127;
        const int g   = idx >> 7;              // d-octet
        const float* gp = qb + (size_t)(8 * g) * NSEQ + i0 + i;
        float v[8];
        #pragma unroll
        for (int s = 0; s < 8; s++) v[s] = gp[(size_t)s * NSEQ] * QSCALE;
        uint4 w;
        w.x = pack_h2(v[0], v[1]); w.y = pack_h2(v[2], v[3]);
        w.z = pack_h2(v[4], v[5]); w.w = pack_h2(v[6], v[7]);
        *(uint4*)(Su + i * 32 + ((4 * g) ^ (4 * (i & 7)))) = w;
    }
    __syncthreads();

    // ---- Q fragments -> registers (32 regs: fp16x2 pairs along d) ----
    uint32_t qf[2][4][4];
    {
        const int sw = 4 * grp;
        #pragma unroll
        for (int mt = 0; mt < 2; mt++) {
            const int row = r0 + 16 * mt + grp;
            const uint32_t* q0 = Su + row * 32;
            const uint32_t* q1 = q0 + 8 * 32;
            #pragma unroll
            for (int ks = 0; ks < 4; ks++) {
                qf[mt][ks][0] = q0[(8 * ks + tg) ^ sw];
                qf[mt][ks][1] = q1[(8 * ks + tg) ^ sw];
                qf[mt][ks][2] = q0[(8 * ks + 4 + tg) ^ sw];
                qf[mt][ks][3] = q1[(8 * ks + 4 + tg) ^ sw];
            }
        }
    }
    __syncthreads();   // Q staging dead; buffers usable

    float so[2][8][4];
    #pragma unroll
    for (int mt = 0; mt < 2; mt++)
        #pragma unroll
        for (int f = 0; f < 8; f++)
            #pragma unroll
            for (int r = 0; r < 4; r++) so[mt][f][r] = 0.f;
    float lr[2][2] = {{0.f, 0.f}, {0.f, 0.f}};

    // ---- fill(buf, j0): K rows=j cols=d-pairs, V rows=dd cols=j-pairs ----
    #define FILL_TILE(buf, j0) do { \
        uint32_t* Ksf = Su + (buf) * BUFU; \
        uint32_t* Vsf = Ksf + 2048; \
        _Pragma("unroll") \
        for (int it = 0; it < 4; it++) { \
            const int idx = it * NTHREADS + tid; \
            const int j   = idx & 63; \
            const int g   = idx >> 6; \
            const float* gp = kb + (size_t)(8 * g) * NSEQ + (j0) + j; \
            float v[8]; \
            _Pragma("unroll") \
            for (int s = 0; s < 8; s++) v[s] = gp[(size_t)s * NSEQ]; \
            uint4 w; \
            w.x = pack_h2(v[0], v[1]); w.y = pack_h2(v[2], v[3]); \
            w.z = pack_h2(v[4], v[5]); w.w = pack_h2(v[6], v[7]); \
            *(uint4*)(Ksf + j * 32 + ((4 * g) ^ (4 * (j & 7)))) = w; \
        } \
        _Pragma("unroll") \
        for (int it = 0; it < 4; it++) { \
            const int idx = it * NTHREADS + tid; \
            const int dd  = idx >> 3; \
            const int g   = idx & 7; \
            const float* vp = vb + (size_t)dd * NSEQ + (j0) + 8 * g; \
            const float4 v0 = *(const float4*)(vp); \
            const float4 v1 = *(const float4*)(vp + 4); \
            uint4 w; \
            w.x = pack_h2(v0.x, v0.y); w.y = pack_h2(v0.z, v0.w); \
            w.z = pack_h2(v1.x, v1.y); w.w = pack_h2(v1.z, v1.w); \
            *(uint4*)(Vsf + dd * 32 + ((4 * g) ^ (4 * (dd & 7)))) = w; \
        } \
        if (tid < TK) mS[(buf) * 64 + tid] = mask[b * NSEQ + (j0) + tid]; \
    } while (0)

    FILL_TILE(0, 0);

    for (int t = 0; t < 16; t++) {
        const int p = t & 1;
        const uint32_t* Ksu = Su + p * BUFU;
        const uint32_t* Vsu = Ksu + 2048;
        __syncthreads();   // fill(t) visible; GEMM2(t-1) done with buf p^1

        // ---- GEMM1: S = Q K^T, fp16 k16, 64 MMAs, 16 independent chains ----
        float sc[2][8][4];
        #pragma unroll
        for (int mt = 0; mt < 2; mt++)
            #pragma unroll
            for (int f = 0; f < 8; f++)
                #pragma unroll
                for (int r = 0; r < 4; r++) sc[mt][f][r] = 0.f;

        const int swb = 4 * grp;
        #pragma unroll
        for (int ks = 0; ks < 4; ks++) {
            #pragma unroll
            for (int f = 0; f < 8; f++) {
                const uint32_t* krow = Ksu + (8 * f + grp) * 32;
                const uint32_t b0 = krow[(8 * ks + tg) ^ swb];
                const uint32_t b1 = krow[(8 * ks + 4 + tg) ^ swb];
                MMA_F16(sc[0][f], qf[0][ks], b0, b1);
                MMA_F16(sc[1][f], qf[1][ks], b0, b1);
            }
        }

        // ---- softmax: bare ex2 (log2e folded into Q); masked to 0 ----
        #pragma unroll
        for (int f = 0; f < 8; f++) {
            const int c0 = 8 * f + 2 * tg;
            const bool m0 = (mS[p * 64 + c0] != 0u), m1 = (mS[p * 64 + c0 + 1] != 0u);
            #pragma unroll
            for (int mt = 0; mt < 2; mt++) {
                const float p0 = m0 ? ex2f(sc[mt][f][0]) : 0.f;
                const float p1 = m1 ? ex2f(sc[mt][f][1]) : 0.f;
                const float p2 = m0 ? ex2f(sc[mt][f][2]) : 0.f;
                const float p3 = m1 ? ex2f(sc[mt][f][3]) : 0.f;
                lr[mt][0] += p0 + p1;
                lr[mt][1] += p2 + p3;
                sc[mt][f][0] = p0; sc[mt][f][1] = p1;
                sc[mt][f][2] = p2; sc[mt][f][3] = p3;
            }
        }

        // ---- pack ALL P -> fp16 A-frags (sc dead after this) ----
        uint32_t ap[4][2][4];
        #pragma unroll
        for (int kp = 0; kp < 4; kp++)
            #pragma unroll
            for (int mt = 0; mt < 2; mt++) {
                ap[kp][mt][0] = pack_h2(sc[mt][2 * kp][0],     sc[mt][2 * kp][1]);
                ap[kp][mt][1] = pack_h2(sc[mt][2 * kp][2],     sc[mt][2 * kp][3]);
                ap[kp][mt][2] = pack_h2(sc[mt][2 * kp + 1][0], sc[mt][2 * kp + 1][1]);
                ap[kp][mt][3] = pack_h2(sc[mt][2 * kp + 1][2], sc[mt][2 * kp + 1][3]);
            }

        // ---- prefetch fill(t+1) into buffer p^1 (overlaps GEMM2) ----
        if (t < 15) FILL_TILE(p ^ 1, (t + 1) * TK);

        // ---- GEMM2: O += P V^T, 64 MMAs ----
        #pragma unroll
        for (int kp = 0; kp < 4; kp++) {
            #pragma unroll
            for (int f = 0; f < 8; f++) {
                const uint32_t* vrow = Vsu + (8 * f + grp) * 32;
                const uint32_t b0 = vrow[(8 * kp + tg)     ^ swb];
                const uint32_t b1 = vrow[(8 * kp + 4 + tg) ^ swb];
                MMA_F16(so[0][f], ap[kp][0], b0, b1);
                MMA_F16(so[1][f], ap[kp][1], b0, b1);
            }
        }
    }

    // ---- epilogue: l reduce, normalize, transpose via smem, coalesced store ----
    #pragma unroll
    for (int mt = 0; mt < 2; mt++)
        #pragma unroll
        for (int hh = 0; hh < 2; hh++) {
            lr[mt][hh] += __shfl_xor_sync(0xffffffffu, lr[mt][hh], 1);
            lr[mt][hh] += __shfl_xor_sync(0xffffffffu, lr[mt][hh], 2);
        }
    float inv[2][2];
    #pragma unroll
    for (int mt = 0; mt < 2; mt++) {
        inv[mt][0] = 1.0f / lr[mt][0];
        inv[mt][1] = 1.0f / lr[mt][1];
    }

    __syncthreads();   // all GEMM2 done; smem reusable
    float* Os = smem;  // [dd][i] 64x128 fp32, swizzle i' = i ^ ((dd&6)<<2)
    #pragma unroll
    for (int f = 0; f < 8; f++) {
        const int dd = 8 * f + 2 * tg;
        const int sw = (dd & 6) << 2;
        #pragma unroll
        for (int mt = 0; mt < 2; mt++) {
            const int row = (r0 + 16 * mt + grp) ^ sw;
            Os[dd * 128 + row]             = so[mt][f][0] * inv[mt][0];
            Os[(dd + 1) * 128 + row]       = so[mt][f][1] * inv[mt][0];
            Os[dd * 128 + (row ^ 8)]       = so[mt][f][2] * inv[mt][1];
            Os[(dd + 1) * 128 + (row ^ 8)] = so[mt][f][3] * inv[mt][1];
        }
    }
    __syncthreads();

    float* ob = out + ((size_t)b * 1024 + h * 64) * NSEQ + i0;
    #pragma unroll
    for (int it = 0; it < 16; it++) {
        const int lin = it * 512 + tid * 4;
        const int dd  = lin >> 7;
        const int c   = lin & 127;
        const float4 v = *(const float4*)(Os + dd * 128 + c);
        *(float4*)(ob + (size_t)dd * NSEQ + (c ^ ((dd & 6) << 2))) = v;
    }
}

extern "C" void kernel_launch(void* const* d_in, const int* in_sizes, int n_in,
                              void* d_out, int out_size)
{
    const float* qkv = (const float*)d_in[0];
    const unsigned int* mask = (const unsigned int*)d_in[1];
    float* out = (float*)d_out;

    cudaFuncSetAttribute(attn_mma_kernel,
                         cudaFuncAttributeMaxDynamicSharedMemorySize, SMEM_BYTES);

    dim3 grid(NSEQ / TQ, 64);
    attn_mma_kernel<<<grid, NTHREADS, SMEM_BYTES>>>(qkv, mask, out);
}

// round 15
// speedup vs baseline: 1.3388x; 1.1254x over previous
#include <cuda_runtime.h>
#include <cstdint>
#include <math.h>

// QKV attention, full fp16 mma.sync m16n8k16 (fp32 accum). R12 structure
// (4 warps, 32x64 warp tile, single-buffer, 2 syncs/tile) + ldmatrix.x4
// B-fragment loads (128 LDS -> 32 ldmatrix per tile/warp) + ex2 softmax
// (log2e folded into Q) + pack fused into softmax (sc dies early).
// qkv (4, 3*1024, 1024) fp32, 16 heads, d=64. CTA = 128 queries x full seq.

#define NSEQ 1024
#define TQ   128
#define TK   64
#define NTHREADS 128

// smem (uint32 units): Ks16[64][32] @0 | Vs16[64][32] @2048 | mask @4096.
// Qs16[128][32] staging and Os fp32[64][128] epilogue alias. 32KB total.
#define OU_K 0
#define OU_V 2048
#define OU_M 4096
#define SMEM_BYTES 32768

// 1/sqrt(64) * log2(e): softmax is bare ex2
#define QSCALE 0.18033688011112042f

__device__ __forceinline__ uint32_t pack_h2(float lo, float hi) {
    uint32_t r; asm("cvt.rn.f16x2.f32 %0, %1, %2;" : "=r"(r) : "f"(hi), "f"(lo));
    return r;
}
__device__ __forceinline__ float ex2f(float x) {
    float r; asm("ex2.approx.f32 %0, %1;" : "=f"(r) : "f"(x)); return r;
}

#define MMA_F16(c, a, b0, b1) \
    asm volatile("mma.sync.aligned.m16n8k16.row.col.f32.f16.f16.f32 " \
        "{%0,%1,%2,%3}, {%4,%5,%6,%7}, {%8,%9}, {%0,%1,%2,%3};" \
        : "+f"((c)[0]), "+f"((c)[1]), "+f"((c)[2]), "+f"((c)[3]) \
        : "r"((a)[0]), "r"((a)[1]), "r"((a)[2]), "r"((a)[3]), "r"(b0), "r"(b1))

#define LDMX4(r, addr) \
    asm volatile("ldmatrix.sync.aligned.m8n8.x4.shared.b16 {%0,%1,%2,%3}, [%4];" \
        : "=r"((r)[0]), "=r"((r)[1]), "=r"((r)[2]), "=r"((r)[3]) : "r"(addr))

extern __shared__ float smem[];

__global__ void __launch_bounds__(NTHREADS, 2)
attn_mma_kernel(const float* __restrict__ qkv,
                const unsigned int* __restrict__ mask,
                float* __restrict__ out)
{
    uint32_t* Ksu = (uint32_t*)smem + OU_K;
    uint32_t* Vsu = (uint32_t*)smem + OU_V;
    unsigned int* mS = (uint32_t*)smem + OU_M;

    const int tid  = threadIdx.x;
    const int lane = tid & 31;
    const int warp = tid >> 5;              // 0..3, rows 32*warp..+31
    const int grp  = lane >> 2;
    const int tg   = lane & 3;
    const int r0   = 32 * warp;

    const int bh = blockIdx.y, b = bh >> 4, h = bh & 15;
    const int i0 = blockIdx.x * TQ;

    const float* qb = qkv + ((size_t)b * 3072 + h * 64) * NSEQ;
    const float* kb = qb + (size_t)1024 * NSEQ;
    const float* vb = qb + (size_t)2048 * NSEQ;

    // ---- stage Q: rows=i (128), 32 d-pair cols, swizzle col ^ 4*(i&7) ----
    uint32_t* Qsu = (uint32_t*)smem;
    #pragma unroll
    for (int it = 0; it < 8; it++) {
        const int idx = it * NTHREADS + tid;   // 0..1023
        const int i   = idx & 127;
        const int g   = idx >> 7;              // d-octet
        const float* gp = qb + (size_t)(8 * g) * NSEQ + i0 + i;
        float v[8];
        #pragma unroll
        for (int s = 0; s < 8; s++) v[s] = gp[(size_t)s * NSEQ] * QSCALE;
        uint4 w;
        w.x = pack_h2(v[0], v[1]); w.y = pack_h2(v[2], v[3]);
        w.z = pack_h2(v[4], v[5]); w.w = pack_h2(v[6], v[7]);
        *(uint4*)(Qsu + i * 32 + ((4 * g) ^ (4 * (i & 7)))) = w;
    }
    __syncthreads();

    // ---- Q fragments -> registers (32 regs: fp16x2 pairs along d) ----
    uint32_t qf[2][4][4];
    {
        const int sw = 4 * grp;
        #pragma unroll
        for (int mt = 0; mt < 2; mt++) {
            const int row = r0 + 16 * mt + grp;
            const uint32_t* q0 = Qsu + row * 32;
            const uint32_t* q1 = q0 + 8 * 32;
            #pragma unroll
            for (int ks = 0; ks < 4; ks++) {
                qf[mt][ks][0] = q0[(8 * ks + tg) ^ sw];
                qf[mt][ks][1] = q1[(8 * ks + tg) ^ sw];
                qf[mt][ks][2] = q0[(8 * ks + 4 + tg) ^ sw];
                qf[mt][ks][3] = q1[(8 * ks + 4 + tg) ^ sw];
            }
        }
    }
    __syncthreads();   // Q staging dead; Ks/Vs usable

    float so[2][8][4];
    #pragma unroll
    for (int mt = 0; mt < 2; mt++)
        #pragma unroll
        for (int f = 0; f < 8; f++)
            #pragma unroll
            for (int r = 0; r < 4; r++) so[mt][f][r] = 0.f;
    float lr[2][2] = {{0.f, 0.f}, {0.f, 0.f}};

    // ---- ldmatrix lane address pattern (byte offsets within a 64-row tile)
    //      tile(f, colgroup c): row jr of matrix ti at
    //      f*1024 + jr*128 + ((16*(c0+ti)) ^ (16*jr)); lanes: ti=l/8, jr=l%8.
    const int ti = lane >> 3, jr = lane & 7;
    const uint32_t lmo1 = (uint32_t)(jr * 128 + ((16 * ti) ^ (16 * jr)));
    const uint32_t lmo2 = (uint32_t)(jr * 128 + ((16 * (ti + 4)) ^ (16 * jr)));
    const uint32_t ksb = (uint32_t)__cvta_generic_to_shared(Ksu);
    const uint32_t vsb = (uint32_t)__cvta_generic_to_shared(Vsu);

    for (int t = 0; t < 16; t++) {
        const int j0 = t * TK;
        __syncthreads();   // prev tile's GEMMs done reading Ks/Vs

        // ---- K fill: rows=j, cols=d-pairs, swizzle col ^ 4*(j&7) ----
        #pragma unroll
        for (int it = 0; it < 4; it++) {
            const int idx = it * NTHREADS + tid;   // 0..511
            const int j   = idx & 63;
            const int g   = idx >> 6;              // d-octet
            const float* gp = kb + (size_t)(8 * g) * NSEQ + j0 + j;
            float v[8];
            #pragma unroll
            for (int s = 0; s < 8; s++) v[s] = gp[(size_t)s * NSEQ];
            uint4 w;
            w.x = pack_h2(v[0], v[1]); w.y = pack_h2(v[2], v[3]);
            w.z = pack_h2(v[4], v[5]); w.w = pack_h2(v[6], v[7]);
            *(uint4*)(Ksu + j * 32 + ((4 * g) ^ (4 * (j & 7)))) = w;
        }
        // ---- V fill: rows=dd, cols=j-pairs, swizzle col ^ 4*(dd&7) ----
        #pragma unroll
        for (int it = 0; it < 4; it++) {
            const int idx = it * NTHREADS + tid;   // 0..511
            const int dd  = idx >> 3;
            const int g   = idx & 7;               // j-octet
            const float* vp = vb + (size_t)dd * NSEQ + j0 + 8 * g;
            const float4 v0 = *(const float4*)(vp);
            const float4 v1 = *(const float4*)(vp + 4);
            uint4 w;
            w.x = pack_h2(v0.x, v0.y); w.y = pack_h2(v0.z, v0.w);
            w.z = pack_h2(v1.x, v1.y); w.w = pack_h2(v1.z, v1.w);
            *(uint4*)(Vsu + dd * 32 + ((4 * g) ^ (4 * (dd & 7)))) = w;
        }
        if (tid < TK) mS[tid] = mask[b * NSEQ + j0 + tid];
        __syncthreads();

        // ---- GEMM1: S = Q K^T; f-pairs, ldmatrix.x4 B-frags ----
        float sc[2][8][4];
        #pragma unroll
        for (int mt = 0; mt < 2; mt++)
            #pragma unroll
            for (int f = 0; f < 8; f++)
                #pragma unroll
                for (int r = 0; r < 4; r++) sc[mt][f][r] = 0.f;

        #pragma unroll
        for (int fg = 0; fg < 8; fg += 2) {
            uint32_t k0[8], k1[8];
            const uint32_t a0 = ksb + fg * 1024;
            const uint32_t a1 = a0 + 1024;
            LDMX4(k0,     a0 + lmo1);
            LDMX4(k0 + 4, a0 + lmo2);
            LDMX4(k1,     a1 + lmo1);
            LDMX4(k1 + 4, a1 + lmo2);
            #pragma unroll
            for (int ks = 0; ks < 4; ks++) {
                MMA_F16(sc[0][fg],     qf[0][ks], k0[2 * ks], k0[2 * ks + 1]);
                MMA_F16(sc[1][fg],     qf[1][ks], k0[2 * ks], k0[2 * ks + 1]);
                MMA_F16(sc[0][fg + 1], qf[0][ks], k1[2 * ks], k1[2 * ks + 1]);
                MMA_F16(sc[1][fg + 1], qf[1][ks], k1[2 * ks], k1[2 * ks + 1]);
            }
        }

        // ---- softmax (bare ex2) + pack fused: sc dies progressively ----
        uint32_t ap[4][2][4];
        #pragma unroll
        for (int kp = 0; kp < 4; kp++) {
            #pragma unroll
            for (int f2 = 0; f2 < 2; f2++) {
                const int f  = 2 * kp + f2;
                const int c0 = 8 * f + 2 * tg;
                const bool m0 = (mS[c0] != 0u), m1 = (mS[c0 + 1] != 0u);
                #pragma unroll
                for (int mt = 0; mt < 2; mt++) {
                    const float p0 = m0 ? ex2f(sc[mt][f][0]) : 0.f;
                    const float p1 = m1 ? ex2f(sc[mt][f][1]) : 0.f;
                    const float p2 = m0 ? ex2f(sc[mt][f][2]) : 0.f;
                    const float p3 = m1 ? ex2f(sc[mt][f][3]) : 0.f;
                    lr[mt][0] += p0 + p1;
                    lr[mt][1] += p2 + p3;
                    ap[kp][mt][2 * f2]     = pack_h2(p0, p1);
                    ap[kp][mt][2 * f2 + 1] = pack_h2(p2, p3);
                }
            }
        }

        // ---- GEMM2: O += P V^T; f-quads, ldmatrix.x4 B-frags ----
        #pragma unroll
        for (int fg = 0; fg < 8; fg += 4) {
            uint32_t vf[4][8];
            #pragma unroll
            for (int fl = 0; fl < 4; fl++) {
                const uint32_t a0 = vsb + (fg + fl) * 1024;
                LDMX4(vf[fl],     a0 + lmo1);
                LDMX4(vf[fl] + 4, a0 + lmo2);
            }
            #pragma unroll
            for (int kp = 0; kp < 4; kp++) {
                #pragma unroll
                for (int fl = 0; fl < 4; fl++) {
                    MMA_F16(so[0][fg + fl], ap[kp][0], vf[fl][2 * kp], vf[fl][2 * kp + 1]);
                    MMA_F16(so[1][fg + fl], ap[kp][1], vf[fl][2 * kp], vf[fl][2 * kp + 1]);
                }
            }
        }
    }

    // ---- epilogue: l reduce, normalize, transpose via smem, coalesced store ----
    #pragma unroll
    for (int mt = 0; mt < 2; mt++)
        #pragma unroll
        for (int hh = 0; hh < 2; hh++) {
            lr[mt][hh] += __shfl_xor_sync(0xffffffffu, lr[mt][hh], 1);
            lr[mt][hh] += __shfl_xor_sync(0xffffffffu, lr[mt][hh], 2);
        }
    float inv[2][2];
    #pragma unroll
    for (int mt = 0; mt < 2; mt++) {
        inv[mt][0] = 1.0f / lr[mt][0];
        inv[mt][1] = 1.0f / lr[mt][1];
    }

    __syncthreads();   // all GEMM2 done; smem reusable
    float* Os = smem;  // [dd][i] 64x128 fp32, swizzle i' = i ^ ((dd&6)<<2)
    #pragma unroll
    for (int f = 0; f < 8; f++) {
        const int dd = 8 * f + 2 * tg;
        const int sw = (dd & 6) << 2;
        #pragma unroll
        for (int mt = 0; mt < 2; mt++) {
            const int row = (r0 + 16 * mt + grp) ^ sw;
            Os[dd * 128 + row]             = so[mt][f][0] * inv[mt][0];
            Os[(dd + 1) * 128 + row]       = so[mt][f][1] * inv[mt][0];
            Os[dd * 128 + (row ^ 8)]       = so[mt][f][2] * inv[mt][1];
            Os[(dd + 1) * 128 + (row ^ 8)] = so[mt][f][3] * inv[mt][1];
        }
    }
    __syncthreads();

    float* ob = out + ((size_t)b * 1024 + h * 64) * NSEQ + i0;
    #pragma unroll
    for (int it = 0; it < 16; it++) {
        const int lin = it * 512 + tid * 4;
        const int dd  = lin >> 7;
        const int c   = lin & 127;
        const float4 v = *(const float4*)(Os + dd * 128 + c);
        *(float4*)(ob + (size_t)dd * NSEQ + (c ^ ((dd & 6) << 2))) = v;
    }
}

extern "C" void kernel_launch(void* const* d_in, const int* in_sizes, int n_in,
                              void* d_out, int out_size)
{
    const float* qkv = (const float*)d_in[0];
    const unsigned int* mask = (const unsigned int*)d_in[1];
    float* out = (float*)d_out;

    cudaFuncSetAttribute(attn_mma_kernel,
                         cudaFuncAttributeMaxDynamicSharedMemorySize, SMEM_BYTES);

    dim3 grid(NSEQ / TQ, 64);
    attn_mma_kernel<<<grid, NTHREADS, SMEM_BYTES>>>(qkv, mask, out);
}